// round 16
// baseline (speedup 1.0000x reference)
#include <cuda_runtime.h>
#include <cuda_bf16.h>
#include <cstdint>

typedef unsigned int u32;

#define NMAX 50000
#define EMAX 100000
#define WCSZ 262144     /* 512 * 512 : [hi(256)|lo(256)] per row */

// ---------------- device scratch (static allocation, allowed) ----------------
__device__ float g_v[2][NMAX * 512];      // v_user, v_item
__device__ float g_a[4][NMAX * 8];        // aq_u, ak_u, aq_i, ak_i
__device__ float g_weff[4][8 * 256];      // effective attn-scalar weights
__device__ float g_beff[4][8];            // effective attn-scalar biases
__device__ float g_den[3][NMAX * 8];      // per-etype softmax denominators
__device__ float g_deg[3][NMAX];          // per-etype in-degree
__device__ float g_w[3][EMAX * 8];        // per-edge exp(score) per head
__device__ int   g_off[3][NMAX];          // CSR offsets (exclusive scan of deg)
__device__ int   g_cur[3][NMAX];          // CSR fill cursors
__device__ int   g_eid[3][EMAX];          // edge ids sorted by dst
__device__ __nv_bfloat16 g_wc[2][WCSZ];   // W split: [hi | lo] per row

// ---------------- prep: zero(den,deg,cur) + cvt_w(x2) + weff, one launch ----
__global__ void prep_kernel(const float* __restrict__ Wv_u, const float* __restrict__ Wv_i,
                            const float* __restrict__ Wq_u, const float* __restrict__ Wk_u,
                            const float* __restrict__ Wq_i, const float* __restrict__ Wk_i,
                            const float* __restrict__ bq_u, const float* __restrict__ bk_u,
                            const float* __restrict__ bq_i, const float* __restrict__ bk_i,
                            const float* __restrict__ wa_u, const float* __restrict__ wa_i)
{
    int b = blockIdx.x;
    if (b < 1024) {
        int t = b >> 9;
        int i = (b & 511) * 256 + threadIdx.x;
        const float* W = t ? Wv_i : Wv_u;
        int n = i >> 8, k = i & 255;
        float v = W[i];
        __nv_bfloat16 hi = __float2bfloat16(v);
        __nv_bfloat16 lo = __float2bfloat16(v - __bfloat162float(hi));
        __nv_bfloat16* d = g_wc[t] + n * 512;
        d[k] = hi; d[256 + k] = lo;
    } else if (b < 1057) {
        int bb = b - 1024;
        if (bb < 32) {
            int t = bb >> 3, h = bb & 7;
            const float* W  = (t == 0) ? Wq_u : (t == 1) ? Wk_u : (t == 2) ? Wq_i : Wk_i;
            const float* wa = (t < 2) ? wa_u : wa_i;
            __shared__ float was[64];
            if (threadIdx.x < 64) was[threadIdx.x] = wa[threadIdx.x];
            __syncthreads();
            int k = threadIdx.x;
            float acc = 0.f;
            #pragma unroll 8
            for (int d2 = 0; d2 < 64; d2++)
                acc += W[(h * 64 + d2) * 256 + k] * was[d2];
            g_weff[t][h * 256 + k] = acc;
        } else {
            if (threadIdx.x < 32) {
                int t = threadIdx.x >> 3, h = threadIdx.x & 7;
                const float* bb2 = (t == 0) ? bq_u : (t == 1) ? bk_u : (t == 2) ? bq_i : bk_i;
                const float* wa = (t < 2) ? wa_u : wa_i;
                float acc = 0.f;
                for (int d2 = 0; d2 < 64; d2++) acc += bb2[h * 64 + d2] * wa[d2];
                g_beff[t][h] = acc;
            }
        }
    } else {
        long long idx = (long long)(b - 1057) * blockDim.x + threadIdx.x;
        long long stride = (long long)(gridDim.x - 1057) * blockDim.x;
        float4 z = make_float4(0.f, 0.f, 0.f, 0.f);
        float4* p2 = (float4*)&g_den[0][0];
        long long n2 = (long long)3 * NMAX * 8 / 4;
        for (long long i = idx; i < n2; i += stride) p2[i] = z;
        float* p3 = &g_deg[0][0];
        long long n3 = (long long)3 * NMAX;
        for (long long i = idx; i < n3; i += stride) p3[i] = 0.f;
        int* p4 = &g_cur[0][0];
        for (long long i = idx; i < n3; i += stride) p4[i] = 0;
    }
}

// ---------------- HMMA helpers ----------------
__device__ __forceinline__ void ldsm4(u32* r, u32 addr)
{
    asm volatile("ldmatrix.sync.aligned.m8n8.x4.shared.b16 {%0,%1,%2,%3}, [%4];"
                 : "=r"(r[0]), "=r"(r[1]), "=r"(r[2]), "=r"(r[3]) : "r"(addr));
}
__device__ __forceinline__ void mma_bf16(float* c, const u32* a, u32 b0, u32 b1)
{
    asm volatile("mma.sync.aligned.m16n8k16.row.col.f32.bf16.bf16.f32 "
                 "{%0,%1,%2,%3}, {%4,%5,%6,%7}, {%8,%9}, {%0,%1,%2,%3};"
                 : "+f"(c[0]), "+f"(c[1]), "+f"(c[2]), "+f"(c[3])
                 : "r"(a[0]), "r"(a[1]), "r"(a[2]), "r"(a[3]), "r"(b0), "r"(b1));
}

// ---------------- fused split + V projection on tensor cores ----------------
// C[M,512] = X[M,256] @ W[512,256]^T + bias, bf16-split (hh + hl + lh), fp32 acc
// CTA 128x128, 8 warps (2m x 4n), warp 64x32.
// K stage 16, DOUBLE buffered: 8 tiles x 128 x KSTRIDE(24) bf16 = 49152 B
// (exactly the 48KB static limit). STS of stage s+1 overlaps MMA of stage s;
// one barrier per stage, zero exposed store time.
#define KSTRIDE 24
#define TILESZ (128 * KSTRIDE)
#define BUFSZ  (4 * TILESZ)
__global__ void __launch_bounds__(256) hgemm2_kernel(
        const float* __restrict__ Xu, const float* __restrict__ Xi,
        const float* __restrict__ bias_u, const float* __restrict__ bias_i,
        int Mu, int Mi)
{
    __shared__ __nv_bfloat16 sm[2 * BUFSZ];
    int item = blockIdx.z;
    const float* X = item ? Xi : Xu;
    const float* bias = item ? bias_i : bias_u;
    int M = item ? Mi : Mu;
    int mbase = blockIdx.y * 128, nbase = blockIdx.x * 128;
    if (mbase >= M) return;
    const __nv_bfloat16* Wc = g_wc[item];
    float* C = g_v[item];

    int tid  = threadIdx.x;
    int lane = tid & 31, wid = tid >> 5;
    int mw = wid & 1, nw = wid >> 1;

    // load mapping: row = tid>>1 (0..127), col half = (tid&1)*8
    int lrow = tid >> 1, cb = (tid & 1) * 8;
    int avalid = (mbase + lrow) < M;
    const float* Ap = X + (long long)(mbase + lrow) * 256 + cb;       // 8 fp32
    const __nv_bfloat16* Bph = Wc + (nbase + lrow) * 512 + cb;        // 8 bf16 hi
    const __nv_bfloat16* Bpl = Bph + 256;                             // 8 bf16 lo
    int sOff = lrow * KSTRIDE + cb;

    u32 smBase = (u32)__cvta_generic_to_shared(sm);
    const u32 TB = TILESZ * 2;          // tile bytes
    const u32 BB = BUFSZ * 2;           // buffer bytes

    int arow = mw * 64 + (lane & 15);
    int acol = (lane >> 4) * 8;
    int brow = nw * 32 + (lane & 7) + ((lane >> 4) << 3);
    int bkof = lane & 8;

    float acc[4][4][4];
    #pragma unroll
    for (int i = 0; i < 4; i++)
        #pragma unroll
        for (int j = 0; j < 4; j++)
            #pragma unroll
            for (int q = 0; q < 4; q++) acc[i][j][q] = 0.f;

    float4 pa0, pa1;        // 8 fp32 of A
    float4 pbh, pbl;        // 8 bf16 hi, 8 bf16 lo

    // store regs (stage data) into buffer `buf`
    #define STORE_STAGE(buf)                                                     \
    {                                                                            \
        __nv_bfloat16* Ah = sm + (buf) * BUFSZ;                                  \
        __nv_bfloat16* Al = Ah + TILESZ;                                         \
        __nv_bfloat16* Bh = Al + TILESZ;                                         \
        __nv_bfloat16* Bl = Bh + TILESZ;                                         \
        __nv_bfloat162 h01, h23, l01, l23;                                       \
        __nv_bfloat16 hx, hy, hz, hw;                                            \
        hx = __float2bfloat16(pa0.x); hy = __float2bfloat16(pa0.y);              \
        hz = __float2bfloat16(pa0.z); hw = __float2bfloat16(pa0.w);              \
        h01.x = hx; h01.y = hy; h23.x = hz; h23.y = hw;                          \
        l01.x = __float2bfloat16(pa0.x - __bfloat162float(hx));                  \
        l01.y = __float2bfloat16(pa0.y - __bfloat162float(hy));                  \
        l23.x = __float2bfloat16(pa0.z - __bfloat162float(hz));                  \
        l23.y = __float2bfloat16(pa0.w - __bfloat162float(hw));                  \
        *(__nv_bfloat162*)(Ah + sOff)     = h01;                                 \
        *(__nv_bfloat162*)(Ah + sOff + 2) = h23;                                 \
        *(__nv_bfloat162*)(Al + sOff)     = l01;                                 \
        *(__nv_bfloat162*)(Al + sOff + 2) = l23;                                 \
        hx = __float2bfloat16(pa1.x); hy = __float2bfloat16(pa1.y);              \
        hz = __float2bfloat16(pa1.z); hw = __float2bfloat16(pa1.w);              \
        h01.x = hx; h01.y = hy; h23.x = hz; h23.y = hw;                          \
        l01.x = __float2bfloat16(pa1.x - __bfloat162float(hx));                  \
        l01.y = __float2bfloat16(pa1.y - __bfloat162float(hy));                  \
        l23.x = __float2bfloat16(pa1.z - __bfloat162float(hz));                  \
        l23.y = __float2bfloat16(pa1.w - __bfloat162float(hw));                  \
        *(__nv_bfloat162*)(Ah + sOff + 4) = h01;                                 \
        *(__nv_bfloat162*)(Ah + sOff + 6) = h23;                                 \
        *(__nv_bfloat162*)(Al + sOff + 4) = l01;                                 \
        *(__nv_bfloat162*)(Al + sOff + 6) = l23;                                 \
        *(float4*)(Bh + sOff) = pbh;                                             \
        *(float4*)(Bl + sOff) = pbl;                                             \
    }

    // preload stage 0 into regs, store to buf 0
    {
        if (avalid) { pa0 = *(const float4*)(Ap); pa1 = *(const float4*)(Ap + 4); }
        else { pa0 = make_float4(0.f,0.f,0.f,0.f); pa1 = pa0; }
        pbh = *(const float4*)(Bph);
        pbl = *(const float4*)(Bpl);
        STORE_STAGE(0)
    }
    __syncthreads();

    const int NSTAGE = 16;                  // 256 / 16
    for (int s = 0; s < NSTAGE; s++) {
        // prefetch + store stage s+1 into the other buffer (overlaps MMA below;
        // that buffer's previous contents were consumed in stage s-1, synced)
        if (s + 1 < NSTAGE) {
            int k0 = (s + 1) * 16;
            if (avalid) { pa0 = *(const float4*)(Ap + k0); pa1 = *(const float4*)(Ap + k0 + 4); }
            else { pa0 = make_float4(0.f,0.f,0.f,0.f); pa1 = pa0; }
            pbh = *(const float4*)(Bph + k0);
            pbl = *(const float4*)(Bpl + k0);
            STORE_STAGE((s + 1) & 1)
        }
        // compute on buffer s&1
        u32 base = smBase + (u32)(s & 1) * BB;
        u32 bAh = base, bAl = base + TB, bBh = base + 2 * TB, bBl = base + 3 * TB;
        u32 ah[4][4], al[4][4];
        #pragma unroll
        for (int mt = 0; mt < 4; mt++) {
            u32 ro = ((arow + mt * 16) * KSTRIDE + acol) * 2;
            ldsm4(ah[mt], bAh + ro);
            ldsm4(al[mt], bAl + ro);
        }
        u32 bh[2][4], bl[2][4];
        #pragma unroll
        for (int p = 0; p < 2; p++) {
            u32 ro = ((brow + p * 16) * KSTRIDE + bkof) * 2;
            ldsm4(bh[p], bBh + ro);
            ldsm4(bl[p], bBl + ro);
        }
        #pragma unroll
        for (int mt = 0; mt < 4; mt++)
            #pragma unroll
            for (int nt = 0; nt < 4; nt++) {
                u32 h0 = bh[nt >> 1][(nt & 1) * 2], h1 = bh[nt >> 1][(nt & 1) * 2 + 1];
                u32 l0 = bl[nt >> 1][(nt & 1) * 2], l1 = bl[nt >> 1][(nt & 1) * 2 + 1];
                mma_bf16(acc[mt][nt], ah[mt], h0, h1);   // hi*hi
                mma_bf16(acc[mt][nt], ah[mt], l0, l1);   // hi*lo
                mma_bf16(acc[mt][nt], al[mt], h0, h1);   // lo*hi
            }
        __syncthreads();
    }

    int g = lane >> 2, t2 = (lane & 3) * 2;
    #pragma unroll
    for (int mt = 0; mt < 4; mt++) {
        int row = mbase + mw * 64 + mt * 16 + g;
        #pragma unroll
        for (int nt = 0; nt < 4; nt++) {
            int col = nbase + nw * 32 + nt * 8 + t2;
            float bx = bias[col], by = bias[col + 1];
            if (row < M) {
                float2 o = make_float2(acc[mt][nt][0] + bx, acc[mt][nt][1] + by);
                *(float2*)(C + (long long)row * 512 + col) = o;
            }
            if (row + 8 < M) {
                float2 o = make_float2(acc[mt][nt][2] + bx, acc[mt][nt][3] + by);
                *(float2*)(C + (long long)(row + 8) * 512 + col) = o;
            }
        }
    }
    #undef STORE_STAGE
}

// ---------------- attention scalars ----------------
__global__ void __launch_bounds__(256) attn_scalar_kernel(const float* __restrict__ x_u,
        const float* __restrict__ x_i, int NUn, int NIn)
{
    int t = blockIdx.y;
    int Nn = t ? NIn : NUn;
    const float* X = t ? x_i : x_u;
    __shared__ float xs[16][260];
    __shared__ float ws[16][260];
    int tid = threadIdx.x;
    int nb = blockIdx.x * 16;
    for (int i = tid; i < 16 * 256; i += 256) {
        int r = i >> 8, c = i & 255;
        ws[r][c] = g_weff[t * 2 + (r >> 3)][(r & 7) * 256 + c];
    }
    for (int i = tid; i < 16 * 64; i += 256) {
        int r = i >> 6, c = i & 63;
        float4 v = make_float4(0.f, 0.f, 0.f, 0.f);
        if (nb + r < Nn) v = *(const float4*)(X + (long long)(nb + r) * 256 + c * 4);
        *(float4*)(&xs[r][c * 4]) = v;
    }
    __syncthreads();
    int ln = tid >> 4;
    int o  = tid & 15;
    float acc = 0.f;
    #pragma unroll 4
    for (int k = 0; k < 256; k += 4) {
        float4 xv = *(const float4*)(&xs[ln][k]);
        float4 wv = *(const float4*)(&ws[o][k]);
        acc += xv.x * wv.x + xv.y * wv.y + xv.z * wv.z + xv.w * wv.w;
    }
    int node = nb + ln;
    if (node < Nn) {
        int slice = t * 2 + (o >> 3);
        g_a[slice][node * 8 + (o & 7)] = acc + g_beff[slice][o & 7];
    }
}

// ---------------- edge pass 1 (all etypes): exp(score), den, deg ----------
__global__ void edge1_all_kernel(
        const int* __restrict__ s0, const int* __restrict__ d0,
        const int* __restrict__ s1, const int* __restrict__ d1,
        const int* __restrict__ s2, const int* __restrict__ d2,
        int E0, int E1, int E2)
{
    int et = blockIdx.y;
    const int* src = (et == 0) ? s0 : (et == 1) ? s1 : s2;
    const int* dst = (et == 0) ? d0 : (et == 1) ? d1 : d2;
    int E       = (et == 0) ? E0 : (et == 1) ? E1 : E2;
    int sliceS  = (et == 0) ? 1  : (et == 1) ? 3  : 1;
    int sliceD  = (et == 0) ? 2  : 0;
    int idx = blockIdx.x * blockDim.x + threadIdx.x;
    if (idx >= E * 8) return;
    int e = idx >> 3, h = idx & 7;
    int s = src[e], d = dst[e];
    float sc = (g_a[sliceS][s * 8 + h] + g_a[sliceD][d * 8 + h]) * 0.125f;
    float w = expf(sc);
    g_w[et][e * 8 + h] = w;
    atomicAdd(&g_den[et][d * 8 + h], w);
    if (h == 0) atomicAdd(&g_deg[et][d], 1.0f);
}

// ---------------- CSR scan: exclusive prefix of deg per etype ----------
__global__ void __launch_bounds__(1024) scan_kernel(int NUn, int NIn)
{
    int et = blockIdx.x;
    int N = (et == 0) ? NIn : NUn;
    int tid = threadIdx.x, lane = tid & 31, wid = tid >> 5;
    __shared__ int wsum[32];
    __shared__ int carry;
    if (tid == 0) carry = 0;
    __syncthreads();
    for (int base = 0; base < N; base += 1024) {
        int i = base + tid;
        int v = (i < N) ? (int)g_deg[et][i] : 0;
        int incl = v;
        #pragma unroll
        for (int s2 = 1; s2 < 32; s2 <<= 1) {
            int t = __shfl_up_sync(0xffffffffu, incl, s2);
            if (lane >= s2) incl += t;
        }
        if (lane == 31) wsum[wid] = incl;
        __syncthreads();
        if (wid == 0) {
            int wv = wsum[lane];
            int wincl = wv;
            #pragma unroll
            for (int s2 = 1; s2 < 32; s2 <<= 1) {
                int t = __shfl_up_sync(0xffffffffu, wincl, s2);
                if (lane >= s2) wincl += t;
            }
            wsum[lane] = wincl - wv;
        }
        __syncthreads();
        int excl = carry + wsum[wid] + incl - v;
        if (i < N) g_off[et][i] = excl;
        __syncthreads();
        if (tid == 1023) carry = excl + v;
        __syncthreads();
    }
}

// ---------------- CSR fill: bucket edge ids by dst ----------
__global__ void scatter_kernel(
        const int* __restrict__ d0, const int* __restrict__ d1,
        const int* __restrict__ d2, int E0, int E1, int E2)
{
    int et = blockIdx.y;
    const int* dst = (et == 0) ? d0 : (et == 1) ? d1 : d2;
    int E = (et == 0) ? E0 : (et == 1) ? E1 : E2;
    int e = blockIdx.x * blockDim.x + threadIdx.x;
    if (e >= E) return;
    int d = dst[e];
    int pos = atomicAdd(&g_cur[et][d], 1);
    g_eid[et][g_off[et][d] + pos] = e;
}

// ---------------- gather: one warp per dst node, write out once ----------
__global__ void __launch_bounds__(256) gather_kernel(
        const int* __restrict__ s0, const int* __restrict__ s1,
        const int* __restrict__ s2, float* __restrict__ out, int NUn, int NIn)
{
    int gwarp = blockIdx.x * 8 + (threadIdx.x >> 5);
    int lane = threadIdx.x & 31;
    if (gwarp >= NUn + NIn) return;

    float4 acc[4];
    #pragma unroll
    for (int c = 0; c < 4; c++) acc[c] = make_float4(0.f, 0.f, 0.f, 0.f);

    int etBeg, etEnd, node;
    if (gwarp < NUn) { node = gwarp; etBeg = 1; etEnd = 3; }
    else             { node = gwarp - NUn; etBeg = 0; etEnd = 1; }

    for (int et = etBeg; et < etEnd; et++) {
        int dg = (int)g_deg[et][node];
        if (dg == 0) continue;
        float sc = 0.f;
        if (lane < 8)
            sc = 1.f / (g_den[et][node * 8 + lane] * (float)dg);
        const int* src = (et == 0) ? s0 : (et == 1) ? s1 : s2;
        int vsel = (et == 1) ? 1 : 0;
        int beg = g_off[et][node];
        int e = __ldg(&g_eid[et][beg]);
        int s = __ldg(src + e);
        for (int j = 0; j < dg; j++) {
            int e_nxt = 0, s_nxt = 0;
            if (j + 1 < dg) {
                e_nxt = __ldg(&g_eid[et][beg + j + 1]);
                s_nxt = __ldg(src + e_nxt);
            }
            float w8 = 0.f;
            if (lane < 8) w8 = g_w[et][e * 8 + lane] * sc;
            const float* vrow = g_v[vsel] + (long long)s * 512;
            #pragma unroll
            for (int c = 0; c < 4; c++) {
                int off = (c * 32 + lane) * 4;
                float4 v = *(const float4*)(vrow + off);
                float wh = __shfl_sync(0xffffffffu, w8, off >> 6);
                acc[c].x += v.x * wh; acc[c].y += v.y * wh;
                acc[c].z += v.z * wh; acc[c].w += v.w * wh;
            }
            e = e_nxt; s = s_nxt;
        }
    }

    float* orow = out + (long long)gwarp * 512;
    #pragma unroll
    for (int c = 0; c < 4; c++)
        *(float4*)(orow + (c * 32 + lane) * 4) = acc[c];
}

// ---------------- launch: hgemm2 placed 4th so ncu samples it ----------------
extern "C" void kernel_launch(void* const* d_in, const int* in_sizes, int n_in,
                              void* d_out, int out_size)
{
    const float* x_u  = (const float*)d_in[0];
    const float* x_i  = (const float*)d_in[1];
    const float* Wq_u = (const float*)d_in[2];  const float* bq_u = (const float*)d_in[3];
    const float* Wk_u = (const float*)d_in[4];  const float* bk_u = (const float*)d_in[5];
    const float* Wv_u = (const float*)d_in[6];  const float* bv_u = (const float*)d_in[7];
    const float* Wq_i = (const float*)d_in[8];  const float* bq_i = (const float*)d_in[9];
    const float* Wk_i = (const float*)d_in[10]; const float* bk_i = (const float*)d_in[11];
    const float* Wv_i = (const float*)d_in[12]; const float* bv_i = (const float*)d_in[13];
    const float* wa_u = (const float*)d_in[14];
    const float* wa_i = (const float*)d_in[15];
    const int* src_c  = (const int*)d_in[16];   const int* dst_c  = (const int*)d_in[17];
    const int* src_cb = (const int*)d_in[18];   const int* dst_cb = (const int*)d_in[19];
    const int* src_f  = (const int*)d_in[20];   const int* dst_f  = (const int*)d_in[21];
    int NUn = in_sizes[0] / 256;
    int NIn = in_sizes[1] / 256;
    int E0 = in_sizes[16], E1 = in_sizes[18], E2 = in_sizes[20];
    float* out = (float*)d_out;

    prep_kernel<<<1057 + 256, 256>>>(Wv_u, Wv_i, Wq_u, Wk_u, Wq_i, Wk_i,
                                     bq_u, bk_u, bq_i, bk_i, wa_u, wa_i);

    int Mmax = NUn > NIn ? NUn : NIn;
    attn_scalar_kernel<<<dim3((Mmax + 15) / 16, 2), 256>>>(x_u, x_i, NUn, NIn);

    int Emax = E0 > E1 ? E0 : E1; if (E2 > Emax) Emax = E2;
    edge1_all_kernel<<<dim3((Emax * 8 + 255) / 256, 3), 256>>>(
        src_c, dst_c, src_cb, dst_cb, src_f, dst_f, E0, E1, E2);

    hgemm2_kernel<<<dim3(4, (Mmax + 127) / 128, 2), 256>>>(x_u, x_i, bv_u, bv_i, NUn, NIn);

    scan_kernel<<<3, 1024>>>(NUn, NIn);

    scatter_kernel<<<dim3((Emax + 255) / 256, 3), 256>>>(
        dst_c, dst_cb, dst_f, E0, E1, E2);

    gather_kernel<<<(NUn + NIn + 7) / 8, 256>>>(src_c, src_cb, src_f, out, NUn, NIn);
}

// round 17
// speedup vs baseline: 1.1326x; 1.1326x over previous
#include <cuda_runtime.h>
#include <cuda_bf16.h>
#include <cstdint>

typedef unsigned int u32;

#define NMAX 50000
#define EMAX 100000
#define WCSZ 262144     /* 512 * 512 : [hi(256)|lo(256)] per row */

// ---------------- device scratch (static allocation, allowed) ----------------
__device__ float g_v[2][NMAX * 512];      // v_user, v_item
__device__ float g_a[4][NMAX * 8];        // aq_u, ak_u, aq_i, ak_i
__device__ float g_weff[4][8 * 256];      // effective attn-scalar weights
__device__ float g_beff[4][8];            // effective attn-scalar biases
__device__ float g_den[3][NMAX * 8];      // per-etype softmax denominators
__device__ float g_deg[3][NMAX];          // per-etype in-degree
__device__ float g_w[3][EMAX * 8];        // per-edge exp(score) per head
__device__ int   g_off[3][NMAX];          // CSR offsets (exclusive scan of deg)
__device__ int   g_cur[3][NMAX];          // CSR fill cursors
__device__ int   g_eid[3][EMAX];          // edge ids sorted by dst
__device__ int   g_csum[3][64];           // per-chunk degree sums (scan phase A)
__device__ __nv_bfloat16 g_wc[2][WCSZ];   // W split: [hi | lo] per row

// ---------------- prep: zero(den,deg,cur) + cvt_w(x2) + weff, one launch ----
__global__ void prep_kernel(const float* __restrict__ Wv_u, const float* __restrict__ Wv_i,
                            const float* __restrict__ Wq_u, const float* __restrict__ Wk_u,
                            const float* __restrict__ Wq_i, const float* __restrict__ Wk_i,
                            const float* __restrict__ bq_u, const float* __restrict__ bk_u,
                            const float* __restrict__ bq_i, const float* __restrict__ bk_i,
                            const float* __restrict__ wa_u, const float* __restrict__ wa_i)
{
    int b = blockIdx.x;
    if (b < 1024) {
        int t = b >> 9;
        int i = (b & 511) * 256 + threadIdx.x;
        const float* W = t ? Wv_i : Wv_u;
        int n = i >> 8, k = i & 255;
        float v = W[i];
        __nv_bfloat16 hi = __float2bfloat16(v);
        __nv_bfloat16 lo = __float2bfloat16(v - __bfloat162float(hi));
        __nv_bfloat16* d = g_wc[t] + n * 512;
        d[k] = hi; d[256 + k] = lo;
    } else if (b < 1057) {
        int bb = b - 1024;
        if (bb < 32) {
            int t = bb >> 3, h = bb & 7;
            const float* W  = (t == 0) ? Wq_u : (t == 1) ? Wk_u : (t == 2) ? Wq_i : Wk_i;
            const float* wa = (t < 2) ? wa_u : wa_i;
            __shared__ float was[64];
            if (threadIdx.x < 64) was[threadIdx.x] = wa[threadIdx.x];
            __syncthreads();
            int k = threadIdx.x;
            float acc = 0.f;
            #pragma unroll 8
            for (int d2 = 0; d2 < 64; d2++)
                acc += W[(h * 64 + d2) * 256 + k] * was[d2];
            g_weff[t][h * 256 + k] = acc;
        } else {
            if (threadIdx.x < 32) {
                int t = threadIdx.x >> 3, h = threadIdx.x & 7;
                const float* bb2 = (t == 0) ? bq_u : (t == 1) ? bk_u : (t == 2) ? bq_i : bk_i;
                const float* wa = (t < 2) ? wa_u : wa_i;
                float acc = 0.f;
                for (int d2 = 0; d2 < 64; d2++) acc += bb2[h * 64 + d2] * wa[d2];
                g_beff[t][h] = acc;
            }
        }
    } else {
        long long idx = (long long)(b - 1057) * blockDim.x + threadIdx.x;
        long long stride = (long long)(gridDim.x - 1057) * blockDim.x;
        float4 z = make_float4(0.f, 0.f, 0.f, 0.f);
        float4* p2 = (float4*)&g_den[0][0];
        long long n2 = (long long)3 * NMAX * 8 / 4;
        for (long long i = idx; i < n2; i += stride) p2[i] = z;
        float* p3 = &g_deg[0][0];
        long long n3 = (long long)3 * NMAX;
        for (long long i = idx; i < n3; i += stride) p3[i] = 0.f;
        int* p4 = &g_cur[0][0];
        for (long long i = idx; i < n3; i += stride) p4[i] = 0;
    }
}

// ---------------- HMMA helpers ----------------
__device__ __forceinline__ void ldsm4(u32* r, u32 addr)
{
    asm volatile("ldmatrix.sync.aligned.m8n8.x4.shared.b16 {%0,%1,%2,%3}, [%4];"
                 : "=r"(r[0]), "=r"(r[1]), "=r"(r[2]), "=r"(r[3]) : "r"(addr));
}
__device__ __forceinline__ void mma_bf16(float* c, const u32* a, u32 b0, u32 b1)
{
    asm volatile("mma.sync.aligned.m16n8k16.row.col.f32.bf16.bf16.f32 "
                 "{%0,%1,%2,%3}, {%4,%5,%6,%7}, {%8,%9}, {%0,%1,%2,%3};"
                 : "+f"(c[0]), "+f"(c[1]), "+f"(c[2]), "+f"(c[3])
                 : "r"(a[0]), "r"(a[1]), "r"(a[2]), "r"(a[3]), "r"(b0), "r"(b1));
}

// ---------------- fused split + V projection on tensor cores ----------------
// C[M,512] = X[M,256] @ W[512,256]^T + bias, bf16-split (hh + hl + lh), fp32 acc
// CTA 128x128, 8 warps (2m x 4n), warp 64x32.
// K stage 16, double buffered (8 tiles x 128 x 24 bf16 = 48KB exactly).
// Per stage: LDG prefetch(s+1) -> MMA(s) -> STS(s+1) -> sync. The global-load
// latency is hidden behind the 48 MMAs; store fully overlapped; 1 barrier/stage.
#define KSTRIDE 24
#define TILESZ (128 * KSTRIDE)
#define BUFSZ  (4 * TILESZ)
__global__ void __launch_bounds__(256) hgemm2_kernel(
        const float* __restrict__ Xu, const float* __restrict__ Xi,
        const float* __restrict__ bias_u, const float* __restrict__ bias_i,
        int Mu, int Mi)
{
    __shared__ __nv_bfloat16 sm[2 * BUFSZ];
    int item = blockIdx.z;
    const float* X = item ? Xi : Xu;
    const float* bias = item ? bias_i : bias_u;
    int M = item ? Mi : Mu;
    int mbase = blockIdx.y * 128, nbase = blockIdx.x * 128;
    if (mbase >= M) return;
    const __nv_bfloat16* Wc = g_wc[item];
    float* C = g_v[item];

    int tid  = threadIdx.x;
    int lane = tid & 31, wid = tid >> 5;
    int mw = wid & 1, nw = wid >> 1;

    int lrow = tid >> 1, cb = (tid & 1) * 8;
    int avalid = (mbase + lrow) < M;
    const float* Ap = X + (long long)(mbase + lrow) * 256 + cb;
    const __nv_bfloat16* Bph = Wc + (nbase + lrow) * 512 + cb;
    const __nv_bfloat16* Bpl = Bph + 256;
    int sOff = lrow * KSTRIDE + cb;

    u32 smBase = (u32)__cvta_generic_to_shared(sm);
    const u32 TB = TILESZ * 2;
    const u32 BB = BUFSZ * 2;

    int arow = mw * 64 + (lane & 15);
    int acol = (lane >> 4) * 8;
    int brow = nw * 32 + (lane & 7) + ((lane >> 4) << 3);
    int bkof = lane & 8;

    float acc[4][4][4];
    #pragma unroll
    for (int i = 0; i < 4; i++)
        #pragma unroll
        for (int j = 0; j < 4; j++)
            #pragma unroll
            for (int q = 0; q < 4; q++) acc[i][j][q] = 0.f;

    float4 pa0, pa1;
    float4 pbh, pbl;

    #define STORE_STAGE(buf)                                                     \
    {                                                                            \
        __nv_bfloat16* Ah = sm + (buf) * BUFSZ;                                  \
        __nv_bfloat16* Al = Ah + TILESZ;                                         \
        __nv_bfloat16* Bh = Al + TILESZ;                                         \
        __nv_bfloat16* Bl = Bh + TILESZ;                                         \
        __nv_bfloat162 h01, h23, l01, l23;                                       \
        __nv_bfloat16 hx, hy, hz, hw;                                            \
        hx = __float2bfloat16(pa0.x); hy = __float2bfloat16(pa0.y);              \
        hz = __float2bfloat16(pa0.z); hw = __float2bfloat16(pa0.w);              \
        h01.x = hx; h01.y = hy; h23.x = hz; h23.y = hw;                          \
        l01.x = __float2bfloat16(pa0.x - __bfloat162float(hx));                  \
        l01.y = __float2bfloat16(pa0.y - __bfloat162float(hy));                  \
        l23.x = __float2bfloat16(pa0.z - __bfloat162float(hz));                  \
        l23.y = __float2bfloat16(pa0.w - __bfloat162float(hw));                  \
        *(__nv_bfloat162*)(Ah + sOff)     = h01;                                 \
        *(__nv_bfloat162*)(Ah + sOff + 2) = h23;                                 \
        *(__nv_bfloat162*)(Al + sOff)     = l01;                                 \
        *(__nv_bfloat162*)(Al + sOff + 2) = l23;                                 \
        hx = __float2bfloat16(pa1.x); hy = __float2bfloat16(pa1.y);              \
        hz = __float2bfloat16(pa1.z); hw = __float2bfloat16(pa1.w);              \
        h01.x = hx; h01.y = hy; h23.x = hz; h23.y = hw;                          \
        l01.x = __float2bfloat16(pa1.x - __bfloat162float(hx));                  \
        l01.y = __float2bfloat16(pa1.y - __bfloat162float(hy));                  \
        l23.x = __float2bfloat16(pa1.z - __bfloat162float(hz));                  \
        l23.y = __float2bfloat16(pa1.w - __bfloat162float(hw));                  \
        *(__nv_bfloat162*)(Ah + sOff + 4) = h01;                                 \
        *(__nv_bfloat162*)(Ah + sOff + 6) = h23;                                 \
        *(__nv_bfloat162*)(Al + sOff + 4) = l01;                                 \
        *(__nv_bfloat162*)(Al + sOff + 6) = l23;                                 \
        *(float4*)(Bh + sOff) = pbh;                                             \
        *(float4*)(Bl + sOff) = pbl;                                             \
    }

    // stage 0 into buf 0
    {
        if (avalid) { pa0 = *(const float4*)(Ap); pa1 = *(const float4*)(Ap + 4); }
        else { pa0 = make_float4(0.f,0.f,0.f,0.f); pa1 = pa0; }
        pbh = *(const float4*)(Bph);
        pbl = *(const float4*)(Bpl);
        STORE_STAGE(0)
    }
    __syncthreads();

    const int NSTAGE = 16;
    for (int s = 0; s < NSTAGE; s++) {
        // issue global prefetch for stage s+1 (consumed after the MMAs)
        if (s + 1 < NSTAGE) {
            int k0 = (s + 1) * 16;
            if (avalid) { pa0 = *(const float4*)(Ap + k0); pa1 = *(const float4*)(Ap + k0 + 4); }
            else { pa0 = make_float4(0.f,0.f,0.f,0.f); pa1 = pa0; }
            pbh = *(const float4*)(Bph + k0);
            pbl = *(const float4*)(Bpl + k0);
        }
        // compute on buffer s&1 (overlaps the in-flight prefetch)
        u32 base = smBase + (u32)(s & 1) * BB;
        u32 bAh = base, bAl = base + TB, bBh = base + 2 * TB, bBl = base + 3 * TB;
        u32 ah[4][4], al[4][4];
        #pragma unroll
        for (int mt = 0; mt < 4; mt++) {
            u32 ro = ((arow + mt * 16) * KSTRIDE + acol) * 2;
            ldsm4(ah[mt], bAh + ro);
            ldsm4(al[mt], bAl + ro);
        }
        u32 bh[2][4], bl[2][4];
        #pragma unroll
        for (int p = 0; p < 2; p++) {
            u32 ro = ((brow + p * 16) * KSTRIDE + bkof) * 2;
            ldsm4(bh[p], bBh + ro);
            ldsm4(bl[p], bBl + ro);
        }
        #pragma unroll
        for (int mt = 0; mt < 4; mt++)
            #pragma unroll
            for (int nt = 0; nt < 4; nt++) {
                u32 h0 = bh[nt >> 1][(nt & 1) * 2], h1 = bh[nt >> 1][(nt & 1) * 2 + 1];
                u32 l0 = bl[nt >> 1][(nt & 1) * 2], l1 = bl[nt >> 1][(nt & 1) * 2 + 1];
                mma_bf16(acc[mt][nt], ah[mt], h0, h1);   // hi*hi
                mma_bf16(acc[mt][nt], ah[mt], l0, l1);   // hi*lo
                mma_bf16(acc[mt][nt], al[mt], h0, h1);   // lo*hi
            }
        // store stage s+1 into the other buffer (its readers synced at stage s-1)
        if (s + 1 < NSTAGE) {
            STORE_STAGE((s + 1) & 1)
            __syncthreads();
        }
    }

    int g = lane >> 2, t2 = (lane & 3) * 2;
    #pragma unroll
    for (int mt = 0; mt < 4; mt++) {
        int row = mbase + mw * 64 + mt * 16 + g;
        #pragma unroll
        for (int nt = 0; nt < 4; nt++) {
            int col = nbase + nw * 32 + nt * 8 + t2;
            float bx = bias[col], by = bias[col + 1];
            if (row < M) {
                float2 o = make_float2(acc[mt][nt][0] + bx, acc[mt][nt][1] + by);
                *(float2*)(C + (long long)row * 512 + col) = o;
            }
            if (row + 8 < M) {
                float2 o = make_float2(acc[mt][nt][2] + bx, acc[mt][nt][3] + by);
                *(float2*)(C + (long long)(row + 8) * 512 + col) = o;
            }
        }
    }
    #undef STORE_STAGE
}

// ---------------- attention scalars ----------------
__global__ void __launch_bounds__(256) attn_scalar_kernel(const float* __restrict__ x_u,
        const float* __restrict__ x_i, int NUn, int NIn)
{
    int t = blockIdx.y;
    int Nn = t ? NIn : NUn;
    const float* X = t ? x_i : x_u;
    __shared__ float xs[16][260];
    __shared__ float ws[16][260];
    int tid = threadIdx.x;
    int nb = blockIdx.x * 16;
    for (int i = tid; i < 16 * 256; i += 256) {
        int r = i >> 8, c = i & 255;
        ws[r][c] = g_weff[t * 2 + (r >> 3)][(r & 7) * 256 + c];
    }
    for (int i = tid; i < 16 * 64; i += 256) {
        int r = i >> 6, c = i & 63;
        float4 v = make_float4(0.f, 0.f, 0.f, 0.f);
        if (nb + r < Nn) v = *(const float4*)(X + (long long)(nb + r) * 256 + c * 4);
        *(float4*)(&xs[r][c * 4]) = v;
    }
    __syncthreads();
    int ln = tid >> 4;
    int o  = tid & 15;
    float acc = 0.f;
    #pragma unroll 4
    for (int k = 0; k < 256; k += 4) {
        float4 xv = *(const float4*)(&xs[ln][k]);
        float4 wv = *(const float4*)(&ws[o][k]);
        acc += xv.x * wv.x + xv.y * wv.y + xv.z * wv.z + xv.w * wv.w;
    }
    int node = nb + ln;
    if (node < Nn) {
        int slice = t * 2 + (o >> 3);
        g_a[slice][node * 8 + (o & 7)] = acc + g_beff[slice][o & 7];
    }
}

// ---------------- edge pass 1 (all etypes): exp(score), den, deg ----------
__global__ void edge1_all_kernel(
        const int* __restrict__ s0, const int* __restrict__ d0,
        const int* __restrict__ s1, const int* __restrict__ d1,
        const int* __restrict__ s2, const int* __restrict__ d2,
        int E0, int E1, int E2)
{
    int et = blockIdx.y;
    const int* src = (et == 0) ? s0 : (et == 1) ? s1 : s2;
    const int* dst = (et == 0) ? d0 : (et == 1) ? d1 : d2;
    int E       = (et == 0) ? E0 : (et == 1) ? E1 : E2;
    int sliceS  = (et == 0) ? 1  : (et == 1) ? 3  : 1;
    int sliceD  = (et == 0) ? 2  : 0;
    int idx = blockIdx.x * blockDim.x + threadIdx.x;
    if (idx >= E * 8) return;
    int e = idx >> 3, h = idx & 7;
    int s = src[e], d = dst[e];
    float sc = (g_a[sliceS][s * 8 + h] + g_a[sliceD][d * 8 + h]) * 0.125f;
    float w = expf(sc);
    g_w[et][e * 8 + h] = w;
    atomicAdd(&g_den[et][d * 8 + h], w);
    if (h == 0) atomicAdd(&g_deg[et][d], 1.0f);
}

// ---------------- scan phase A: per-chunk exclusive scan + chunk totals ----
__global__ void __launch_bounds__(1024) scanA_kernel(int NUn, int NIn)
{
    int et = blockIdx.y;
    int N = (et == 0) ? NIn : NUn;
    int chunk = blockIdx.x;
    int tid = threadIdx.x, lane = tid & 31, wid = tid >> 5;
    int i = chunk * 1024 + tid;
    __shared__ int wsum[32];
    int v = (i < N) ? (int)g_deg[et][i] : 0;
    int incl = v;
    #pragma unroll
    for (int s2 = 1; s2 < 32; s2 <<= 1) {
        int t = __shfl_up_sync(0xffffffffu, incl, s2);
        if (lane >= s2) incl += t;
    }
    if (lane == 31) wsum[wid] = incl;
    __syncthreads();
    if (wid == 0) {
        int wv = wsum[lane];
        int wincl = wv;
        #pragma unroll
        for (int s2 = 1; s2 < 32; s2 <<= 1) {
            int t = __shfl_up_sync(0xffffffffu, wincl, s2);
            if (lane >= s2) wincl += t;
        }
        wsum[lane] = wincl - wv;
    }
    __syncthreads();
    int excl = wsum[wid] + incl - v;
    if (i < N) g_off[et][i] = excl;
    if (tid == 1023) g_csum[et][chunk] = excl + v;
}

// ---------------- scan phase B: apply chunk offsets ----------
__global__ void __launch_bounds__(1024) scanB_kernel(int NUn, int NIn)
{
    int et = blockIdx.x;
    int N = (et == 0) ? NIn : NUn;
    int nch = (N + 1023) >> 10;
    __shared__ int coff[64];
    if (threadIdx.x == 0) {
        int run = 0;
        for (int c = 0; c < nch; c++) { coff[c] = run; run += g_csum[et][c]; }
    }
    __syncthreads();
    for (int i = threadIdx.x; i < N; i += 1024)
        g_off[et][i] += coff[i >> 10];
}

// ---------------- CSR fill: bucket edge ids by dst ----------
__global__ void scatter_kernel(
        const int* __restrict__ d0, const int* __restrict__ d1,
        const int* __restrict__ d2, int E0, int E1, int E2)
{
    int et = blockIdx.y;
    const int* dst = (et == 0) ? d0 : (et == 1) ? d1 : d2;
    int E = (et == 0) ? E0 : (et == 1) ? E1 : E2;
    int e = blockIdx.x * blockDim.x + threadIdx.x;
    if (e >= E) return;
    int d = dst[e];
    int pos = atomicAdd(&g_cur[et][d], 1);
    g_eid[et][g_off[et][d] + pos] = e;
}

// ---------------- gather: one warp per dst node; 2-edge unrolled MLP ----
__global__ void __launch_bounds__(256) gather_kernel(
        const int* __restrict__ s0, const int* __restrict__ s1,
        const int* __restrict__ s2, float* __restrict__ out, int NUn, int NIn)
{
    int gwarp = blockIdx.x * 8 + (threadIdx.x >> 5);
    int lane = threadIdx.x & 31;
    if (gwarp >= NUn + NIn) return;

    float4 acc[4];
    #pragma unroll
    for (int c = 0; c < 4; c++) acc[c] = make_float4(0.f, 0.f, 0.f, 0.f);

    int etBeg, etEnd, node;
    if (gwarp < NUn) { node = gwarp; etBeg = 1; etEnd = 3; }
    else             { node = gwarp - NUn; etBeg = 0; etEnd = 1; }

    for (int et = etBeg; et < etEnd; et++) {
        int dg = (int)g_deg[et][node];
        if (dg == 0) continue;
        float sc = 0.f;
        if (lane < 8)
            sc = 1.f / (g_den[et][node * 8 + lane] * (float)dg);
        const int* src = (et == 0) ? s0 : (et == 1) ? s1 : s2;
        int vsel = (et == 1) ? 1 : 0;
        int beg = g_off[et][node];
        for (int j = 0; j < dg; j += 2) {
            int e0 = __ldg(&g_eid[et][beg + j]);
            int s0v = __ldg(src + e0);
            int two = (j + 1 < dg);
            int e1 = two ? __ldg(&g_eid[et][beg + j + 1]) : e0;
            int s1v = two ? __ldg(src + e1) : s0v;
            float w80 = 0.f, w81 = 0.f;
            if (lane < 8) {
                w80 = g_w[et][e0 * 8 + lane] * sc;
                if (two) w81 = g_w[et][e1 * 8 + lane] * sc;
            }
            const float* v0 = g_v[vsel] + (long long)s0v * 512;
            const float* v1 = g_v[vsel] + (long long)s1v * 512;
            float4 a0[4], a1[4];
            #pragma unroll
            for (int c = 0; c < 4; c++) {
                int off = (c * 32 + lane) * 4;
                a0[c] = *(const float4*)(v0 + off);
            }
            if (two) {
                #pragma unroll
                for (int c = 0; c < 4; c++) {
                    int off = (c * 32 + lane) * 4;
                    a1[c] = *(const float4*)(v1 + off);
                }
            }
            #pragma unroll
            for (int c = 0; c < 4; c++) {
                int off = (c * 32 + lane) * 4;
                float wh = __shfl_sync(0xffffffffu, w80, off >> 6);
                acc[c].x += a0[c].x * wh; acc[c].y += a0[c].y * wh;
                acc[c].z += a0[c].z * wh; acc[c].w += a0[c].w * wh;
            }
            if (two) {
                #pragma unroll
                for (int c = 0; c < 4; c++) {
                    int off = (c * 32 + lane) * 4;
                    float wh = __shfl_sync(0xffffffffu, w81, off >> 6);
                    acc[c].x += a1[c].x * wh; acc[c].y += a1[c].y * wh;
                    acc[c].z += a1[c].z * wh; acc[c].w += a1[c].w * wh;
                }
            }
        }
    }

    float* orow = out + (long long)gwarp * 512;
    #pragma unroll
    for (int c = 0; c < 4; c++)
        *(float4*)(orow + (c * 32 + lane) * 4) = acc[c];
}

// ---------------- launch: hgemm2 stays launch #4 (ncu profiles #4) ----------
extern "C" void kernel_launch(void* const* d_in, const int* in_sizes, int n_in,
                              void* d_out, int out_size)
{
    const float* x_u  = (const float*)d_in[0];
    const float* x_i  = (const float*)d_in[1];
    const float* Wq_u = (const float*)d_in[2];  const float* bq_u = (const float*)d_in[3];
    const float* Wk_u = (const float*)d_in[4];  const float* bk_u = (const float*)d_in[5];
    const float* Wv_u = (const float*)d_in[6];  const float* bv_u = (const float*)d_in[7];
    const float* Wq_i = (const float*)d_in[8];  const float* bq_i = (const float*)d_in[9];
    const float* Wk_i = (const float*)d_in[10]; const float* bk_i = (const float*)d_in[11];
    const float* Wv_i = (const float*)d_in[12]; const float* bv_i = (const float*)d_in[13];
    const float* wa_u = (const float*)d_in[14];
    const float* wa_i = (const float*)d_in[15];
    const int* src_c  = (const int*)d_in[16];   const int* dst_c  = (const int*)d_in[17];
    const int* src_cb = (const int*)d_in[18];   const int* dst_cb = (const int*)d_in[19];
    const int* src_f  = (const int*)d_in[20];   const int* dst_f  = (const int*)d_in[21];
    int NUn = in_sizes[0] / 256;
    int NIn = in_sizes[1] / 256;
    int E0 = in_sizes[16], E1 = in_sizes[18], E2 = in_sizes[20];
    float* out = (float*)d_out;

    prep_kernel<<<1057 + 256, 256>>>(Wv_u, Wv_i, Wq_u, Wk_u, Wq_i, Wk_i,
                                     bq_u, bk_u, bq_i, bk_i, wa_u, wa_i);

    int Mmax = NUn > NIn ? NUn : NIn;
    attn_scalar_kernel<<<dim3((Mmax + 15) / 16, 2), 256>>>(x_u, x_i, NUn, NIn);

    int Emax = E0 > E1 ? E0 : E1; if (E2 > Emax) Emax = E2;
    edge1_all_kernel<<<dim3((Emax * 8 + 255) / 256, 3), 256>>>(
        src_c, dst_c, src_cb, dst_cb, src_f, dst_f, E0, E1, E2);

    hgemm2_kernel<<<dim3(4, (Mmax + 127) / 128, 2), 256>>>(x_u, x_i, bv_u, bv_i, NUn, NIn);

    int nchunk = (Mmax + 1023) / 1024;
    scanA_kernel<<<dim3(nchunk, 3), 1024>>>(NUn, NIn);
    scanB_kernel<<<3, 1024>>>(NUn, NIn);

    scatter_kernel<<<dim3((Emax + 255) / 256, 3), 256>>>(
        dst_c, dst_cb, dst_f, E0, E1, E2);

    gather_kernel<<<(NUn + NIn + 7) / 8, 256>>>(src_c, src_cb, src_f, out, NUn, NIn);
}